// round 8
// baseline (speedup 1.0000x reference)
#include <cuda_runtime.h>
#include <cuda_fp16.h>

// SimpleLSTM: B=4096, T=256, I=16, H=32, O=1 (fp32)
// Two-kernel split:
//  K1: input projection x·W_ih^T + bias for ALL (b,t), gate-scaled (0.5 for
//      i,f,o), stored fp16x4 per (b,t,lane j) in 256MB __device__ scratch.
//  K2: recurrence only (R5 structure): warp = 4 batches, W_hh f32x2 pairs in
//      registers, h broadcast smem dbl-buffer, xg via cp.async dbl-buffer.
//      Per-warp-step FFMA2 drops 384 -> 256.

#define BB 4096
#define TT 256
#define II 16
#define HH 32
#define WARPS_PER_BLK 8
#define THREADS (WARPS_PER_BLK * 32)
#define BPW 4   // batches per warp (K2)

typedef unsigned long long ull;

// 4096*256*32 * 8B = 256 MiB scratch: [b][t][j] -> {h2(i,f), h2(g,o)}
__device__ uint2 g_xg[(long)BB * TT * HH];

__device__ __forceinline__ void ffma2(ull& acc, ull a, ull b) {
    asm("fma.rn.f32x2 %0, %1, %2, %0;" : "+l"(acc) : "l"(a), "l"(b));
}
__device__ __forceinline__ float hadd2(ull v) {
    float lo, hi;
    asm("mov.b64 {%0, %1}, %2;" : "=f"(lo), "=f"(hi) : "l"(v));
    return lo + hi;
}
__device__ __forceinline__ ull pack2(float lo, float hi) {
    ull r;
    asm("mov.b64 %0, {%1, %2};" : "=l"(r) : "f"(lo), "f"(hi));
    return r;
}
__device__ __forceinline__ float tanh_a(float v) {
    float r;
    asm("tanh.approx.f32 %0, %1;" : "=f"(r) : "f"(v));   // MUFU.TANH
    return r;
}
__device__ __forceinline__ void cp_async16(void* smem_dst, const void* gsrc) {
    unsigned saddr = (unsigned)__cvta_generic_to_shared(smem_dst);
    asm volatile("cp.async.ca.shared.global [%0], [%1], 16;" :: "r"(saddr), "l"(gsrc));
}
__device__ __forceinline__ void cp_commit() {
    asm volatile("cp.async.commit_group;" ::: "memory");
}
__device__ __forceinline__ void cp_wait1() {
    asm volatile("cp.async.wait_group 1;" ::: "memory");
}

// ============================ Kernel 1: x-projection ============================
// Warp per batch; lane j computes 4 gate pre-activations per t.
// W_ih slice (4 gates x 16) in registers as f32x2 pairs; x via uniform LDG.128.
__global__ void __launch_bounds__(128)
lstm_xproj_kernel(const float* __restrict__ x,      // [B,T,I]
                  const float* __restrict__ W_ih,   // [4H,I]
                  const float* __restrict__ b_ih,   // [4H]
                  const float* __restrict__ b_hh)   // [4H]
{
    const int w = (blockIdx.x * blockDim.x + threadIdx.x) >> 5;   // batch
    const int j = threadIdx.x & 31;
    if (w >= BB) return;

    const float gsc[4] = {0.5f, 0.5f, 1.0f, 0.5f};   // sigmoid fold i,f,o

    ull  wih2[4][II / 2];
    float bias[4];
    #pragma unroll
    for (int g = 0; g < 4; g++) {
        const float* wr = W_ih + (g * HH + j) * II;
        #pragma unroll
        for (int i2 = 0; i2 < II / 2; i2++)
            wih2[g][i2] = pack2(gsc[g] * wr[2 * i2], gsc[g] * wr[2 * i2 + 1]);
        bias[g] = gsc[g] * (b_ih[g * HH + j] + b_hh[g * HH + j]);
    }

    const ulonglong2* xr = reinterpret_cast<const ulonglong2*>(x + (long)w * TT * II);
    uint2* og = g_xg + (long)w * TT * HH + j;

    // prefetch x(t=0)
    ulonglong2 p0 = xr[0], p1 = xr[1], p2 = xr[2], p3 = xr[3];

    #pragma unroll 1
    for (int t = 0; t < TT; t++) {
        ull xp[8] = {p0.x, p0.y, p1.x, p1.y, p2.x, p2.y, p3.x, p3.y};
        const int tn = (t + 1 < TT) ? t + 1 : t;
        p0 = xr[tn * 4 + 0]; p1 = xr[tn * 4 + 1];
        p2 = xr[tn * 4 + 2]; p3 = xr[tn * 4 + 3];

        ull a0 = 0, a1 = 0, a2 = 0, a3 = 0;
        #pragma unroll
        for (int i2 = 0; i2 < 8; i2++) {
            ffma2(a0, wih2[0][i2], xp[i2]);
            ffma2(a1, wih2[1][i2], xp[i2]);
            ffma2(a2, wih2[2][i2], xp[i2]);
            ffma2(a3, wih2[3][i2], xp[i2]);
        }
        float fi = hadd2(a0) + bias[0];
        float ff = hadd2(a1) + bias[1];
        float fg = hadd2(a2) + bias[2];
        float fo = hadd2(a3) + bias[3];

        __half2 hif = __floats2half2_rn(fi, ff);
        __half2 hgo = __floats2half2_rn(fg, fo);
        uint2 o;
        o.x = *reinterpret_cast<unsigned*>(&hif);
        o.y = *reinterpret_cast<unsigned*>(&hgo);
        og[(long)t * HH] = o;   // warp writes 256B contiguous
    }
}

// ============================ Kernel 2: recurrence ============================
__global__ void __launch_bounds__(THREADS, 1)
lstm_rec_kernel(const float* __restrict__ W_hh,   // [4H,H]
                const float* __restrict__ W_fc,   // [1,H]
                const float* __restrict__ b_fc,   // [1]
                float* __restrict__ out)          // [B,1]
{
    __shared__ float h_s[WARPS_PER_BLK][2][BPW][HH];    // h broadcast, dbl-buffer
    __shared__ uint2 xgs[WARPS_PER_BLK][2][BPW][HH];    // xg staging, dbl-buffer

    const int tid = threadIdx.x;
    const int wid = tid >> 5;
    const int j   = tid & 31;
    const int b0  = (blockIdx.x * WARPS_PER_BLK + wid) * BPW;

    const float gsc[4] = {0.5f, 0.5f, 1.0f, 0.5f};

    // ---- W_hh rows (4 gates) as packed pairs, pre-scaled (128 regs) ----
    ull whh2[4][HH / 2];
    #pragma unroll
    for (int g = 0; g < 4; g++) {
        const float* wrow = W_hh + (g * HH + j) * HH;
        #pragma unroll
        for (int k2 = 0; k2 < HH / 2; k2++)
            whh2[g][k2] = pack2(gsc[g] * wrow[2 * k2], gsc[g] * wrow[2 * k2 + 1]);
    }

    // cp.async mapping: two rounds r=0,1; round r: batch bb = 2r + (lane>>4),
    // 16B chunk (lane&15) within that batch's 256B xg block.
    const int cbb = j >> 4;          // 0..1
    const int cch = (j & 15) * 16;   // byte offset
    const char* gbase0 = reinterpret_cast<const char*>(g_xg + (long)(b0 + 0 + cbb) * TT * HH) + cch;
    const char* gbase2 = reinterpret_cast<const char*>(g_xg + (long)(b0 + 2 + cbb) * TT * HH) + cch;

    float h[BPW] = {0.f, 0.f, 0.f, 0.f};
    float c[BPW] = {0.f, 0.f, 0.f, 0.f};

    // prefetch xg(t=0) into buffer 0
    cp_async16(reinterpret_cast<char*>(&xgs[wid][0][0 + cbb][0]) + cch, gbase0);
    cp_async16(reinterpret_cast<char*>(&xgs[wid][0][2 + cbb][0]) + cch, gbase2);
    cp_commit();

    #pragma unroll 1
    for (int t = 0; t < TT; t++) {
        const int bufx = t & 1;

        // broadcast h (state after step t-1)
        #pragma unroll
        for (int bb = 0; bb < BPW; bb++)
            h_s[wid][bufx][bb][j] = h[bb];

        // prefetch xg(t+1) into other buffer
        const long tn = (t + 1 < TT) ? t + 1 : t;
        cp_async16(reinterpret_cast<char*>(&xgs[wid][bufx ^ 1][0 + cbb][0]) + cch,
                   gbase0 + tn * (HH * 8));
        cp_async16(reinterpret_cast<char*>(&xgs[wid][bufx ^ 1][2 + cbb][0]) + cch,
                   gbase2 + tn * (HH * 8));
        cp_commit();
        cp_wait1();          // current step's xg resident
        __syncwarp();        // h + xg visible warp-wide

        ull ai[BPW] = {0, 0, 0, 0}, af[BPW] = {0, 0, 0, 0};
        ull ag[BPW] = {0, 0, 0, 0}, ao[BPW] = {0, 0, 0, 0};

        // ---- recurrent matvec: register weights, 16 independent chains ----
        #pragma unroll
        for (int kk = 0; kk < 8; kk++) {
            ulonglong2 hq[BPW];
            #pragma unroll
            for (int bb = 0; bb < BPW; bb++)
                hq[bb] = reinterpret_cast<const ulonglong2*>(&h_s[wid][bufx][bb][0])[kk];
            #pragma unroll
            for (int bb = 0; bb < BPW; bb++) {
                ffma2(ai[bb], whh2[0][2*kk], hq[bb].x); ffma2(ai[bb], whh2[0][2*kk+1], hq[bb].y);
                ffma2(af[bb], whh2[1][2*kk], hq[bb].x); ffma2(af[bb], whh2[1][2*kk+1], hq[bb].y);
                ffma2(ag[bb], whh2[2][2*kk], hq[bb].x); ffma2(ag[bb], whh2[2][2*kk+1], hq[bb].y);
                ffma2(ao[bb], whh2[3][2*kk], hq[bb].x); ffma2(ao[bb], whh2[3][2*kk+1], hq[bb].y);
            }
        }

        // ---- add xg, activations (MUFU.TANH), state update ----
        #pragma unroll
        for (int bb = 0; bb < BPW; bb++) {
            uint2 v = xgs[wid][bufx][bb][j];                 // LDS.64, conflict-free
            float2 xif = __half22float2(*reinterpret_cast<__half2*>(&v.x));
            float2 xgo = __half22float2(*reinterpret_cast<__half2*>(&v.y));
            float gi = tanh_a(hadd2(ai[bb]) + xif.x);
            float gf = tanh_a(hadd2(af[bb]) + xif.y);
            float gg = tanh_a(hadd2(ag[bb]) + xgo.x);
            float go = tanh_a(hadd2(ao[bb]) + xgo.y);
            float fi = fmaf(gi, 0.5f, 0.5f);
            float ff = fmaf(gf, 0.5f, 0.5f);
            float fo = fmaf(go, 0.5f, 0.5f);
            c[bb] = fmaf(ff, c[bb], fi * gg);
            h[bb] = fo * tanh_a(c[bb]);
        }
    }

    // ---- final FC (O=1): 4 warp reductions ----
    float wf = W_fc[j];
    float v[BPW];
    #pragma unroll
    for (int bb = 0; bb < BPW; bb++) v[bb] = h[bb] * wf;
    #pragma unroll
    for (int off = 16; off; off >>= 1) {
        #pragma unroll
        for (int bb = 0; bb < BPW; bb++)
            v[bb] += __shfl_xor_sync(0xffffffffu, v[bb], off);
    }
    if (j == 0) {
        float bf = b_fc[0];
        #pragma unroll
        for (int bb = 0; bb < BPW; bb++)
            out[b0 + bb] = v[bb] + bf;
    }
}

extern "C" void kernel_launch(void* const* d_in, const int* in_sizes, int n_in,
                              void* d_out, int out_size) {
    (void)in_sizes; (void)n_in; (void)out_size;
    const float* x    = (const float*)d_in[0];
    const float* W_ih = (const float*)d_in[1];
    const float* W_hh = (const float*)d_in[2];
    const float* b_ih = (const float*)d_in[3];
    const float* b_hh = (const float*)d_in[4];
    const float* W_fc = (const float*)d_in[5];
    const float* b_fc = (const float*)d_in[6];
    float* out = (float*)d_out;

    // K1: 4096 warps (one per batch), 128-thread blocks
    lstm_xproj_kernel<<<BB / 4, 128>>>(x, W_ih, b_ih, b_hh);
    // K2: recurrence (R5 launch shape)
    lstm_rec_kernel<<<BB / (BPW * WARPS_PER_BLK), THREADS>>>(W_hh, W_fc, b_fc, out);
}